// round 12
// baseline (speedup 1.0000x reference)
#include <cuda_runtime.h>
#include <cuda_fp16.h>

#define NUSER 50000
#define NN    100000        // total nodes
#define NNZE  1000000       // edges
#define EPSV  1e-12f
#define SCANB 391           // ceil(NN/256)

// ---------------- scratch (device globals) -----------------------------------
__device__ int    g_deg[NN];
__device__ int    g_pblock[SCANB];    // per-block degree sums -> exclusive prefix
__device__ int    g_rowptr[NN + 1];
__device__ int    g_cursor[NN];
__device__ int    g_dhist[256];       // degree histogram (clamped at 255)
__device__ int    g_dcur[256];        // exclusive prefix / scatter cursor
__device__ int    g_perm[NN];         // nodes sorted by degree
__device__ int    g_tails[NNZE];      // sorted-by-head tail list
__device__ float  g_A[NNZE * 4];      // routing logits (sorted edge order)
__device__ float  g_vals[NNZE * 4];   // softmax(A)
__device__ float  g_d0[NN * 4];       // 1/sqrt(rowsum) ping
__device__ float  g_d1[NN * 4];       // 1/sqrt(rowsum) pong
__device__ uint2  g_h0[NN * 16];      // ego / hn ping  (fp16 x4 per chunk)
__device__ uint2  g_h1[NN * 16];      // ego / hn pong  (fp16 x4)
__device__ uint4  g_tth0[NN * 8];     // tanh tables, layer 0 (fp16)
__device__ uint4  g_tth1[NN * 8];     // tanh tables, layer 1
__device__ float4 g_acc[NN * 16];     // running sum of layer embeddings (fp32)

// fp16x4 <-> float4 helpers
__device__ __forceinline__ float4 ld_h4(const uint2* p, int i) {
    uint2 u = __ldg(&p[i]);
    __half2 a = *reinterpret_cast<__half2*>(&u.x);
    __half2 b = *reinterpret_cast<__half2*>(&u.y);
    float2 fa = __half22float2(a), fb = __half22float2(b);
    return make_float4(fa.x, fa.y, fb.x, fb.y);
}
__device__ __forceinline__ uint2 st_h4(float4 v) {
    __half2 a = __floats2half2_rn(v.x, v.y);
    __half2 b = __floats2half2_rn(v.z, v.w);
    uint2 u;
    u.x = *reinterpret_cast<unsigned*>(&a);
    u.y = *reinterpret_cast<unsigned*>(&b);
    return u;
}

// dot of 16-float hf with 16 fp16 values packed in two uint4
__device__ __forceinline__ float dot16(const float* hf, uint4 ua, uint4 ub) {
    const __half2* pa = reinterpret_cast<const __half2*>(&ua);
    const __half2* pb = reinterpret_cast<const __half2*>(&ub);
    float p0 = 0.f, p1 = 0.f, p2 = 0.f, p3 = 0.f;
    #pragma unroll
    for (int k = 0; k < 4; k++) {
        float2 fa = __half22float2(pa[k]);
        float2 fb = __half22float2(pb[k]);
        p0 = fmaf(hf[2 * k + 0], fa.x, p0);
        p1 = fmaf(hf[2 * k + 1], fa.y, p1);
        p2 = fmaf(hf[8 + 2 * k + 0], fb.x, p2);
        p3 = fmaf(hf[8 + 2 * k + 1], fb.y, p3);
    }
    return (p0 + p1) + (p2 + p3);
}

// ---------------- CSR build ---------------------------------------------------
__global__ void k_zero_deg() {
    int i = blockIdx.x * blockDim.x + threadIdx.x;
    if (i < NN) g_deg[i] = 0;
    if (i < 256) g_dhist[i] = 0;
}

__global__ void k_hist(const int* __restrict__ head) {
    int e = blockIdx.x * blockDim.x + threadIdx.x;
    if (e < NNZE) atomicAdd(&g_deg[head[e]], 1);
}

// phase 1: per-block degree sums (256 degs per block)
__global__ void k_partial() {
    __shared__ int sh[256];
    int i = blockIdx.x * 256 + threadIdx.x;
    sh[threadIdx.x] = (i < NN) ? g_deg[i] : 0;
    __syncthreads();
    for (int off = 128; off > 0; off >>= 1) {
        if (threadIdx.x < off) sh[threadIdx.x] += sh[threadIdx.x + off];
        __syncthreads();
    }
    if (threadIdx.x == 0) g_pblock[blockIdx.x] = sh[0];
}

// phase 2: one block scans the SCANB partials -> exclusive prefixes
__global__ void k_scanpart() {
    __shared__ int sh[512];
    int t = threadIdx.x;                         // 512 threads
    int v = (t < SCANB) ? g_pblock[t] : 0;
    sh[t] = v;
    __syncthreads();
    for (int off = 1; off < 512; off <<= 1) {
        int u = 0;
        if (t >= off) u = sh[t - off];
        __syncthreads();
        if (t >= off) sh[t] += u;
        __syncthreads();
    }
    if (t < SCANB) g_pblock[t] = sh[t] - v;      // exclusive
    if (t == 0) g_rowptr[NN] = NNZE;             // total degree is known
}

// phase 3: local exclusive scan within each 256-chunk + block offset
__global__ void k_rowptr() {
    __shared__ int sh[256];
    int i = blockIdx.x * 256 + threadIdx.x;
    int d = (i < NN) ? g_deg[i] : 0;
    sh[threadIdx.x] = d;
    __syncthreads();
    for (int off = 1; off < 256; off <<= 1) {
        int u = 0;
        if (threadIdx.x >= off) u = sh[threadIdx.x - off];
        __syncthreads();
        if (threadIdx.x >= off) sh[threadIdx.x] += u;
        __syncthreads();
    }
    if (i < NN) {
        int r = g_pblock[blockIdx.x] + sh[threadIdx.x] - d;   // exclusive
        g_rowptr[i] = r;
        g_cursor[i] = r;
    }
}

__global__ void k_scatter(const int* __restrict__ head, const int* __restrict__ tail) {
    int e = blockIdx.x * blockDim.x + threadIdx.x;
    if (e >= NNZE) return;
    int pos = atomicAdd(&g_cursor[head[e]], 1);
    g_tails[pos] = tail[e];
}

// ---------------- degree counting sort (load balancing) -----------------------
__global__ void k_dhist() {
    __shared__ int sh[256];
    sh[threadIdx.x] = 0;
    __syncthreads();
    int i = blockIdx.x * 256 + threadIdx.x;
    if (i < NN) atomicAdd(&sh[min(g_deg[i], 255)], 1);
    __syncthreads();
    if (sh[threadIdx.x]) atomicAdd(&g_dhist[threadIdx.x], sh[threadIdx.x]);
}

__global__ void k_dscan() {
    __shared__ int sh[256];
    int t = threadIdx.x;
    int v = g_dhist[t];
    sh[t] = v;
    __syncthreads();
    for (int off = 1; off < 256; off <<= 1) {
        int u = 0;
        if (t >= off) u = sh[t - off];
        __syncthreads();
        if (t >= off) sh[t] += u;
        __syncthreads();
    }
    g_dcur[t] = sh[t] - v;                       // exclusive
}

__global__ void k_dscatter() {
    int i = blockIdx.x * blockDim.x + threadIdx.x;
    if (i >= NN) return;
    int pos = atomicAdd(&g_dcur[min(g_deg[i], 255)], 1);
    g_perm[pos] = i;
}

// ---------------- init: ego0(fp16), acc(fp32), tt0(fp16), d0 ------------------
__global__ void k_init(const float* __restrict__ user, const float* __restrict__ item) {
    int i = blockIdx.x * blockDim.x + threadIdx.x;   // NN*16 exact
    int n = i >> 4, c = i & 15;
    const float* src = (n < NUSER) ? (user + (size_t)n * 64 + c * 4)
                                   : (item + (size_t)(n - NUSER) * 64 + c * 4);
    float4 v = *reinterpret_cast<const float4*>(src);
    g_h0[i] = st_h4(v);
    g_acc[i] = v;
    float ss = v.x*v.x + v.y*v.y + v.z*v.z + v.w*v.w;
    ss += __shfl_xor_sync(0xffffffffu, ss, 1);
    ss += __shfl_xor_sync(0xffffffffu, ss, 2);
    float inv = 1.f / fmaxf(sqrtf(ss), EPSV);
    reinterpret_cast<uint2*>(g_tth0)[i] =
        st_h4(make_float4(tanhf(v.x*inv), tanhf(v.y*inv), tanhf(v.z*inv), tanhf(v.w*inv)));
    if (c < 4) {
        float s = 0.25f * (float)(g_rowptr[n + 1] - g_rowptr[n]);
        g_d0[n * 4 + c] = (s > 0.f) ? (1.f / sqrtf(fmaxf(s, EPSV))) : 0.f;
    }
}

// ---------------- whole routing iteration (16 lanes per node) -----------------
// nodes processed in degree-sorted order via g_perm (load balancing only;
// each node still computes and writes exactly its own results)
// loop1 lane map: fl=c&3, s=c>>2, chunk=fl*4+s  (group-gather)
// loop2 lane map: e4=c>>2 (edge slot), fl2=c&3  (edge-parallel)
// MODE 0: write hn, scores    MODE 1: + acc, tt1    MODE 2: out only
template<int FIRST, int MODE>
__global__ void k_fused(int xsel, int dsel, int ttsel, float* __restrict__ out) {
    int gid = blockIdx.x * blockDim.x + threadIdx.x;   // NN*16 exact
    int g  = g_perm[gid >> 4];
    int c = gid & 15;
    int fl = c & 3, s = c >> 2;
    int chunk = fl * 4 + s;
    int idx = g * 16 + chunk;

    const uint2* xs = xsel ? g_h1 : g_h0;
    uint2*       hn = xsel ? g_h0 : g_h1;
    const float* dcur  = dsel ? g_d1 : g_d0;
    float*       dnext = dsel ? g_d0 : g_d1;
    const uint4* tt = ttsel ? g_tth1 : g_tth0;

    unsigned gmask = 0xFFFFu << (threadIdx.x & 16);   // 16-lane group

    int beg = g_rowptr[g], end = g_rowptr[g + 1];

    // ---- loop 1: h = l2norm(D A D x); group-gather, 4 edges in flight ----
    float ax = 0.f, ay = 0.f, az = 0.f, aw = 0.f;
    for (int jb = beg; jb < end; jb += 4) {
        #pragma unroll
        for (int k = 0; k < 4; k++) {
            int jj = jb + k;
            bool valid = (jj < end);
            int t = valid ? g_tails[jj] : 0;
            float w = valid ? (FIRST ? 0.25f : g_vals[jj * 4 + fl]) : 0.f;
            float sc = w * dcur[t * 4 + fl];
            float4 x = ld_h4(xs, t * 16 + chunk);
            ax = fmaf(sc, x.x, ax); ay = fmaf(sc, x.y, ay);
            az = fmaf(sc, x.z, az); aw = fmaf(sc, x.w, aw);
        }
    }
    float dn = dcur[g * 4 + fl];
    float fx = dn * ax, fy = dn * ay, fz = dn * az, fw = dn * aw;
    float ss = fx*fx + fy*fy + fz*fz + fw*fw;
    ss += __shfl_xor_sync(gmask, ss, 4);        // reduce over subchunks
    ss += __shfl_xor_sync(gmask, ss, 8);
    float inv = 1.f / fmaxf(sqrtf(ss), EPSV);
    float4 h = make_float4(fx * inv, fy * inv, fz * inv, fw * inv);

    if (MODE == 2) {
        float4 a = g_acc[idx];
        const float k = 1.f / 3.f;
        reinterpret_cast<float4*>(out)[idx] =
            make_float4((a.x + h.x) * k, (a.y + h.y) * k, (a.z + h.z) * k, (a.w + h.w) * k);
        return;
    }
    hn[idx] = st_h4(h);
    if (MODE == 1) {
        float4 a = g_acc[idx];
        g_acc[idx] = make_float4(a.x + h.x, a.y + h.y, a.z + h.z, a.w + h.w);
        reinterpret_cast<uint2*>(g_tth1)[idx] =
            st_h4(make_float4(tanhf(h.x), tanhf(h.y), tanhf(h.z), tanhf(h.w)));
    }

    // ---- broadcast full factor-h into every lane (lane's loop-2 factor) ----
    // chunk m = fl2*4+sp is held by lane (m&3)*4 + (m>>2) = sp*4 + fl2
    float hf[16];
    int fl2 = c & 3;
    #pragma unroll
    for (int sp = 0; sp < 4; sp++) {
        int src = sp * 4 + fl2;
        hf[sp * 4 + 0] = __shfl_sync(gmask, h.x, src, 16);
        hf[sp * 4 + 1] = __shfl_sync(gmask, h.y, src, 16);
        hf[sp * 4 + 2] = __shfl_sync(gmask, h.z, src, 16);
        hf[sp * 4 + 3] = __shfl_sync(gmask, h.w, src, 16);
    }

    // ---- loop 2: 4 edges per iteration, dot in-lane, softmax across fl lanes --
    int e4 = c >> 2;
    int iters = (end - beg + 3) >> 2;
    float rs = 0.f;
    for (int it = 0; it < iters; it++) {
        int jj = beg + it * 4 + e4;
        bool valid = (jj < end);
        int t = valid ? g_tails[jj] : 0;
        const uint4* tp = tt + t * 8 + fl2 * 2;
        uint4 ua = __ldg(tp);
        uint4 ub = __ldg(tp + 1);
        float p = dot16(hf, ua, ub);
        float Aold = valid ? (FIRST ? 1.f : g_A[jj * 4 + fl2]) : 0.f;
        float An = Aold + p;
        if (valid) g_A[jj * 4 + fl2] = An;
        float e0 = __expf(An);                   // no max-shift: |A| <= ~13
        float sm = e0;
        sm += __shfl_xor_sync(gmask, sm, 1);
        sm += __shfl_xor_sync(gmask, sm, 2);
        float v = e0 / sm;
        if (valid) {
            g_vals[jj * 4 + fl2] = v;
            rs += v;
        }
    }
    // rowsum: combine edge slots
    rs += __shfl_xor_sync(gmask, rs, 4);
    rs += __shfl_xor_sync(gmask, rs, 8);
    if (e4 == 0) {
        dnext[g * 4 + fl2] = (rs > 0.f) ? (1.f / sqrtf(fmaxf(rs, EPSV))) : 0.f;
    }
}

// ---------------- launch -------------------------------------------------------
extern "C" void kernel_launch(void* const* d_in, const int* in_sizes, int n_in,
                              void* d_out, int out_size) {
    const float* user = (const float*)d_in[0];
    const float* item = (const float*)d_in[1];
    const int*   head = (const int*)d_in[2];
    const int*   tail = (const int*)d_in[3];
    float* out = (float*)d_out;

    const int TB = 256;
    const int gN   = (NN + TB - 1) / TB;    // = SCANB
    const int gN16 = (NN * 16) / TB;        // exact
    const int gE   = (NNZE + TB - 1) / TB;

    // CSR build (3-phase parallel scan)
    k_zero_deg<<<gN, TB>>>();
    k_hist<<<gE, TB>>>(head);
    k_partial<<<SCANB, 256>>>();
    k_scanpart<<<1, 512>>>();
    k_rowptr<<<SCANB, 256>>>();
    k_scatter<<<gE, TB>>>(head, tail);

    // degree counting sort -> g_perm (load balancing for k_fused)
    k_dhist<<<SCANB, 256>>>();
    k_dscan<<<1, 256>>>();
    k_dscatter<<<gN, TB>>>();

    // ego0 + acc + tt0 + first-iteration d (needs rowptr)
    k_init<<<gN16, TB>>>(user, item);

    //                      xsel dsel ttsel
    k_fused<1, 0><<<gN16, TB>>>(0, 0, 0, out);   // layer0 iter1
    k_fused<0, 1><<<gN16, TB>>>(0, 1, 0, out);   // layer0 iter2: acc+, tt1
    k_fused<0, 0><<<gN16, TB>>>(1, 0, 1, out);   // layer1 iter1
    k_fused<0, 2><<<gN16, TB>>>(1, 1, 1, out);   // layer1 iter2: out
}

// round 13
// speedup vs baseline: 1.1083x; 1.1083x over previous
#include <cuda_runtime.h>
#include <cuda_fp16.h>

#define NUSER 50000
#define NN    100000        // total nodes
#define NNZE  1000000       // edges
#define EPSV  1e-12f
#define SCANB 391           // ceil(NN/256)

// ---------------- scratch (device globals) -----------------------------------
__device__ int    g_deg[NN];
__device__ int    g_pblock[SCANB];    // per-block degree sums -> exclusive prefix
__device__ int    g_rowptr[NN + 1];
__device__ int    g_cursor[NN];
__device__ int    g_tails[NNZE];      // sorted-by-head tail list
__device__ float  g_A[NNZE * 4];      // routing logits (sorted edge order)
__device__ float  g_vals[NNZE * 4];   // softmax(A)
__device__ float  g_d0[NN * 4];       // 1/sqrt(rowsum) ping
__device__ float  g_d1[NN * 4];       // 1/sqrt(rowsum) pong
__device__ uint2  g_h0[NN * 16];      // ego / hn ping  (fp16 x4 per chunk)
__device__ uint2  g_h1[NN * 16];      // ego / hn pong  (fp16 x4)
__device__ uint4  g_tth0[NN * 8];     // tanh tables, layer 0 (fp16)
__device__ uint4  g_tth1[NN * 8];     // tanh tables, layer 1
__device__ float4 g_acc[NN * 16];     // running sum of layer embeddings (fp32)

// fp16x4 <-> float4 helpers
__device__ __forceinline__ float4 ld_h4(const uint2* p, int i) {
    uint2 u = __ldg(&p[i]);
    __half2 a = *reinterpret_cast<__half2*>(&u.x);
    __half2 b = *reinterpret_cast<__half2*>(&u.y);
    float2 fa = __half22float2(a), fb = __half22float2(b);
    return make_float4(fa.x, fa.y, fb.x, fb.y);
}
__device__ __forceinline__ uint2 st_h4(float4 v) {
    __half2 a = __floats2half2_rn(v.x, v.y);
    __half2 b = __floats2half2_rn(v.z, v.w);
    uint2 u;
    u.x = *reinterpret_cast<unsigned*>(&a);
    u.y = *reinterpret_cast<unsigned*>(&b);
    return u;
}

// dot of 16-float hf with 16 fp16 values packed in two uint4
__device__ __forceinline__ float dot16(const float* hf, uint4 ua, uint4 ub) {
    const __half2* pa = reinterpret_cast<const __half2*>(&ua);
    const __half2* pb = reinterpret_cast<const __half2*>(&ub);
    float p0 = 0.f, p1 = 0.f, p2 = 0.f, p3 = 0.f;
    #pragma unroll
    for (int k = 0; k < 4; k++) {
        float2 fa = __half22float2(pa[k]);
        float2 fb = __half22float2(pb[k]);
        p0 = fmaf(hf[2 * k + 0], fa.x, p0);
        p1 = fmaf(hf[2 * k + 1], fa.y, p1);
        p2 = fmaf(hf[8 + 2 * k + 0], fb.x, p2);
        p3 = fmaf(hf[8 + 2 * k + 1], fb.y, p3);
    }
    return (p0 + p1) + (p2 + p3);
}

// ---------------- CSR build ---------------------------------------------------
__global__ void k_zero_deg() {
    int i = blockIdx.x * blockDim.x + threadIdx.x;
    if (i < NN) g_deg[i] = 0;
}

__global__ void k_hist(const int* __restrict__ head) {
    int e = blockIdx.x * blockDim.x + threadIdx.x;
    if (e < NNZE) atomicAdd(&g_deg[head[e]], 1);
}

// phase 1: per-block degree sums (256 degs per block)
__global__ void k_partial() {
    __shared__ int sh[256];
    int i = blockIdx.x * 256 + threadIdx.x;
    sh[threadIdx.x] = (i < NN) ? g_deg[i] : 0;
    __syncthreads();
    for (int off = 128; off > 0; off >>= 1) {
        if (threadIdx.x < off) sh[threadIdx.x] += sh[threadIdx.x + off];
        __syncthreads();
    }
    if (threadIdx.x == 0) g_pblock[blockIdx.x] = sh[0];
}

// phase 2: one block scans the SCANB partials -> exclusive prefixes
__global__ void k_scanpart() {
    __shared__ int sh[512];
    int t = threadIdx.x;                         // 512 threads
    int v = (t < SCANB) ? g_pblock[t] : 0;
    sh[t] = v;
    __syncthreads();
    for (int off = 1; off < 512; off <<= 1) {
        int u = 0;
        if (t >= off) u = sh[t - off];
        __syncthreads();
        if (t >= off) sh[t] += u;
        __syncthreads();
    }
    if (t < SCANB) g_pblock[t] = sh[t] - v;      // exclusive
    if (t == 0) g_rowptr[NN] = NNZE;             // total degree is known
}

// phase 3: local exclusive scan within each 256-chunk + block offset
__global__ void k_rowptr() {
    __shared__ int sh[256];
    int i = blockIdx.x * 256 + threadIdx.x;
    int d = (i < NN) ? g_deg[i] : 0;
    sh[threadIdx.x] = d;
    __syncthreads();
    for (int off = 1; off < 256; off <<= 1) {
        int u = 0;
        if (threadIdx.x >= off) u = sh[threadIdx.x - off];
        __syncthreads();
        if (threadIdx.x >= off) sh[threadIdx.x] += u;
        __syncthreads();
    }
    if (i < NN) {
        int r = g_pblock[blockIdx.x] + sh[threadIdx.x] - d;   // exclusive
        g_rowptr[i] = r;
        g_cursor[i] = r;
    }
}

__global__ void k_scatter(const int* __restrict__ head, const int* __restrict__ tail) {
    int e = blockIdx.x * blockDim.x + threadIdx.x;
    if (e >= NNZE) return;
    int pos = atomicAdd(&g_cursor[head[e]], 1);
    g_tails[pos] = tail[e];
}

// ---------------- init: ego0(fp16), acc(fp32), tt0(fp16), d0 ------------------
__global__ void k_init(const float* __restrict__ user, const float* __restrict__ item) {
    int i = blockIdx.x * blockDim.x + threadIdx.x;   // NN*16 exact
    int n = i >> 4, c = i & 15;
    const float* src = (n < NUSER) ? (user + (size_t)n * 64 + c * 4)
                                   : (item + (size_t)(n - NUSER) * 64 + c * 4);
    float4 v = *reinterpret_cast<const float4*>(src);
    g_h0[i] = st_h4(v);
    g_acc[i] = v;
    float ss = v.x*v.x + v.y*v.y + v.z*v.z + v.w*v.w;
    ss += __shfl_xor_sync(0xffffffffu, ss, 1);
    ss += __shfl_xor_sync(0xffffffffu, ss, 2);
    float inv = 1.f / fmaxf(sqrtf(ss), EPSV);
    reinterpret_cast<uint2*>(g_tth0)[i] =
        st_h4(make_float4(tanhf(v.x*inv), tanhf(v.y*inv), tanhf(v.z*inv), tanhf(v.w*inv)));
    if (c < 4) {
        float s = 0.25f * (float)(g_rowptr[n + 1] - g_rowptr[n]);
        g_d0[n * 4 + c] = (s > 0.f) ? (1.f / sqrtf(fmaxf(s, EPSV))) : 0.f;
    }
}

// ---------------- whole routing iteration (16 lanes per node) -----------------
// loop1 lane map: fl=c&3, s=c>>2, chunk=fl*4+s  (group-gather)
// loop2 lane map: e4=c>>2 (edge slot), fl2=c&3  (edge-parallel, x2 unrolled)
// MODE 0: write hn, scores    MODE 1: + acc, tt1    MODE 2: out only
// softmax: no max-subtraction (|A| <= ~13, exp safely in fp32 range)
template<int FIRST, int MODE>
__global__ void k_fused(int xsel, int dsel, int ttsel, float* __restrict__ out) {
    int gid = blockIdx.x * blockDim.x + threadIdx.x;   // NN*16 exact
    int g  = gid >> 4, c = gid & 15;
    int fl = c & 3, s = c >> 2;
    int chunk = fl * 4 + s;
    int idx = g * 16 + chunk;

    const uint2* xs = xsel ? g_h1 : g_h0;
    uint2*       hn = xsel ? g_h0 : g_h1;
    const float* dcur  = dsel ? g_d1 : g_d0;
    float*       dnext = dsel ? g_d0 : g_d1;
    const uint4* tt = ttsel ? g_tth1 : g_tth0;

    unsigned gmask = 0xFFFFu << (threadIdx.x & 16);   // 16-lane group

    int beg = g_rowptr[g], end = g_rowptr[g + 1];

    // ---- loop 1: h = l2norm(D A D x); group-gather, 4 edges in flight ----
    float ax = 0.f, ay = 0.f, az = 0.f, aw = 0.f;
    for (int jb = beg; jb < end; jb += 4) {
        #pragma unroll
        for (int k = 0; k < 4; k++) {
            int jj = jb + k;
            bool valid = (jj < end);
            int t = valid ? g_tails[jj] : 0;
            float w = valid ? (FIRST ? 0.25f : g_vals[jj * 4 + fl]) : 0.f;
            float sc = w * dcur[t * 4 + fl];
            float4 x = ld_h4(xs, t * 16 + chunk);
            ax = fmaf(sc, x.x, ax); ay = fmaf(sc, x.y, ay);
            az = fmaf(sc, x.z, az); aw = fmaf(sc, x.w, aw);
        }
    }
    float dn = dcur[g * 4 + fl];
    float fx = dn * ax, fy = dn * ay, fz = dn * az, fw = dn * aw;
    float ss = fx*fx + fy*fy + fz*fz + fw*fw;
    ss += __shfl_xor_sync(gmask, ss, 4);        // reduce over subchunks
    ss += __shfl_xor_sync(gmask, ss, 8);
    float inv = 1.f / fmaxf(sqrtf(ss), EPSV);
    float4 h = make_float4(fx * inv, fy * inv, fz * inv, fw * inv);

    if (MODE == 2) {
        float4 a = g_acc[idx];
        const float k = 1.f / 3.f;
        reinterpret_cast<float4*>(out)[idx] =
            make_float4((a.x + h.x) * k, (a.y + h.y) * k, (a.z + h.z) * k, (a.w + h.w) * k);
        return;
    }
    hn[idx] = st_h4(h);
    if (MODE == 1) {
        float4 a = g_acc[idx];
        g_acc[idx] = make_float4(a.x + h.x, a.y + h.y, a.z + h.z, a.w + h.w);
        reinterpret_cast<uint2*>(g_tth1)[idx] =
            st_h4(make_float4(tanhf(h.x), tanhf(h.y), tanhf(h.z), tanhf(h.w)));
    }

    // ---- broadcast full factor-h into every lane (lane's loop-2 factor) ----
    // chunk m = fl2*4+sp is held by lane (m&3)*4 + (m>>2) = sp*4 + fl2
    float hf[16];
    int fl2 = c & 3;
    #pragma unroll
    for (int sp = 0; sp < 4; sp++) {
        int src = sp * 4 + fl2;
        hf[sp * 4 + 0] = __shfl_sync(gmask, h.x, src, 16);
        hf[sp * 4 + 1] = __shfl_sync(gmask, h.y, src, 16);
        hf[sp * 4 + 2] = __shfl_sync(gmask, h.z, src, 16);
        hf[sp * 4 + 3] = __shfl_sync(gmask, h.w, src, 16);
    }

    // ---- loop 2: 8 edges per trip (x2 unroll), dot in-lane, quad softmax ----
    int e4 = c >> 2;
    int iters = (end - beg + 3) >> 2;
    float rs = 0.f;
    int it = 0;
    for (; it + 1 < iters; it += 2) {
        int j0 = beg + it * 4 + e4;
        int j1 = j0 + 4;
        bool v0 = (j0 < end), v1 = (j1 < end);
        int t0 = v0 ? g_tails[j0] : 0;
        int t1 = v1 ? g_tails[j1] : 0;
        const uint4* tp0 = tt + t0 * 8 + fl2 * 2;
        const uint4* tp1 = tt + t1 * 8 + fl2 * 2;
        uint4 ua0 = __ldg(tp0);
        uint4 ub0 = __ldg(tp0 + 1);
        uint4 ua1 = __ldg(tp1);
        uint4 ub1 = __ldg(tp1 + 1);
        float p0 = dot16(hf, ua0, ub0);
        float p1 = dot16(hf, ua1, ub1);
        float A0 = (v0 ? (FIRST ? 1.f : g_A[j0 * 4 + fl2]) : 0.f) + p0;
        float A1 = (v1 ? (FIRST ? 1.f : g_A[j1 * 4 + fl2]) : 0.f) + p1;
        if (v0) g_A[j0 * 4 + fl2] = A0;
        if (v1) g_A[j1 * 4 + fl2] = A1;
        float e0 = __expf(A0);
        float e1 = __expf(A1);
        float s0 = e0, s1 = e1;
        s0 += __shfl_xor_sync(gmask, s0, 1);
        s1 += __shfl_xor_sync(gmask, s1, 1);
        s0 += __shfl_xor_sync(gmask, s0, 2);
        s1 += __shfl_xor_sync(gmask, s1, 2);
        float w0 = e0 / s0;
        float w1 = e1 / s1;
        if (v0) { g_vals[j0 * 4 + fl2] = w0; rs += w0; }
        if (v1) { g_vals[j1 * 4 + fl2] = w1; rs += w1; }
    }
    if (it < iters) {
        int jj = beg + it * 4 + e4;
        bool valid = (jj < end);
        int t = valid ? g_tails[jj] : 0;
        const uint4* tp = tt + t * 8 + fl2 * 2;
        uint4 ua = __ldg(tp);
        uint4 ub = __ldg(tp + 1);
        float p = dot16(hf, ua, ub);
        float An = (valid ? (FIRST ? 1.f : g_A[jj * 4 + fl2]) : 0.f) + p;
        if (valid) g_A[jj * 4 + fl2] = An;
        float e0 = __expf(An);
        float sm = e0;
        sm += __shfl_xor_sync(gmask, sm, 1);
        sm += __shfl_xor_sync(gmask, sm, 2);
        float v = e0 / sm;
        if (valid) {
            g_vals[jj * 4 + fl2] = v;
            rs += v;
        }
    }
    // rowsum: combine edge slots
    rs += __shfl_xor_sync(gmask, rs, 4);
    rs += __shfl_xor_sync(gmask, rs, 8);
    if (e4 == 0) {
        dnext[g * 4 + fl2] = (rs > 0.f) ? (1.f / sqrtf(fmaxf(rs, EPSV))) : 0.f;
    }
}

// ---------------- launch -------------------------------------------------------
extern "C" void kernel_launch(void* const* d_in, const int* in_sizes, int n_in,
                              void* d_out, int out_size) {
    const float* user = (const float*)d_in[0];
    const float* item = (const float*)d_in[1];
    const int*   head = (const int*)d_in[2];
    const int*   tail = (const int*)d_in[3];
    float* out = (float*)d_out;

    const int TB = 256;
    const int gN   = (NN + TB - 1) / TB;    // = SCANB
    const int gN16 = (NN * 16) / TB;        // exact
    const int gE   = (NNZE + TB - 1) / TB;

    // CSR build (3-phase parallel scan)
    k_zero_deg<<<gN, TB>>>();
    k_hist<<<gE, TB>>>(head);
    k_partial<<<SCANB, 256>>>();
    k_scanpart<<<1, 512>>>();
    k_rowptr<<<SCANB, 256>>>();
    k_scatter<<<gE, TB>>>(head, tail);

    // ego0 + acc + tt0 + first-iteration d (needs rowptr)
    k_init<<<gN16, TB>>>(user, item);

    //                      xsel dsel ttsel
    k_fused<1, 0><<<gN16, TB>>>(0, 0, 0, out);   // layer0 iter1
    k_fused<0, 1><<<gN16, TB>>>(0, 1, 0, out);   // layer0 iter2: acc+, tt1
    k_fused<0, 0><<<gN16, TB>>>(1, 0, 1, out);   // layer1 iter1
    k_fused<0, 2><<<gN16, TB>>>(1, 1, 1, out);   // layer1 iter2: out
}